// round 6
// baseline (speedup 1.0000x reference)
#include <cuda_runtime.h>
#include <cstdint>

#define L_DIM 4096
#define B_DIM 4
#define E_DIM 1024
#define H_DIM 16
#define HD 64
#define NH 64            // B*H
#define M_TOT 16384      // L*B
#define EPS_F 1e-4f
#define ANG_C 3.83495196971410283e-4f   // (pi/2)/4096
#define NCHUNK 8

// ---------------- scratch (device globals; no allocs allowed) ----------------
__device__ float g_q[NH * L_DIM * HD];                 // relu(Q) per head-major
__device__ float g_k[NH * L_DIM * HD];                 // relu(K)
__device__ float g_v[NH * L_DIM * HD];                 // V
__device__ float g_xr[3 * M_TOT * E_DIM];              // RNA-rounded, K-permuted X (q,k,v)
__device__ float g_wr[3 * E_DIM * E_DIM];              // RNA-rounded, K-permuted W (q,k,v)
__device__ float g_kv_part[NH * NCHUNK * 2 * HD * HD]; // per-chunk partial kv [d128][m64]
__device__ float g_ks_part[NH * NCHUNK * 2 * HD];      // per-chunk partial ksum [d128]
__device__ float g_kv[NH * 2 * HD * HD];               // reduced kv
__device__ float g_ks[NH * 2 * HD];                    // reduced ksum

__device__ __forceinline__ unsigned f2tf32(float x) {
    unsigned r;
    asm("cvt.rna.tf32.f32 %0, %1;" : "=r"(r) : "f"(x));
    return r;
}
__device__ __forceinline__ float ftf(float x) { return __uint_as_float(f2tf32(x)); }

__device__ __forceinline__ void mma_tf32(float c[4],
                                         unsigned a0, unsigned a1, unsigned a2, unsigned a3,
                                         unsigned b0, unsigned b1) {
    asm volatile(
        "mma.sync.aligned.m16n8k8.row.col.f32.tf32.tf32.f32 "
        "{%0,%1,%2,%3}, {%4,%5,%6,%7}, {%8,%9}, {%0,%1,%2,%3};\n"
        : "+f"(c[0]), "+f"(c[1]), "+f"(c[2]), "+f"(c[3])
        : "r"(a0), "r"(a1), "r"(a2), "r"(a3), "r"(b0), "r"(b1));
}

__device__ __forceinline__ void cpa16(void* dst, const void* src) {
    unsigned d = (unsigned)__cvta_generic_to_shared(dst);
    asm volatile("cp.async.cg.shared.global [%0], [%1], 16;\n" :: "r"(d), "l"(src));
}

// ---------------- Phase 0: RNA-round + K-permute X and W ----------------
// 8-col group [k0..k7] -> [k0,k4,k1,k5,k2,k6,k3,k7] so tf32 frag pairs (k, k+4)
// are adjacent -> one LDS.64 per fragment pair, no CVT in mainloop.
__global__ __launch_bounds__(256) void preround_x(const float4* __restrict__ xq,
                                                  const float4* __restrict__ xk,
                                                  const float4* __restrict__ xv) {
    const int g = blockIdx.x * 256 + threadIdx.x;     // group id, 8 floats each
    const int z = blockIdx.y;
    const float4* src = (z == 0) ? xq : (z == 1) ? xk : xv;
    const float4 g0 = src[2 * g], g1 = src[2 * g + 1];
    float4* dst = (float4*)g_xr + (size_t)z * 4194304 + 2 * g;
    dst[0] = make_float4(ftf(g0.x), ftf(g1.x), ftf(g0.y), ftf(g1.y));
    dst[1] = make_float4(ftf(g0.z), ftf(g1.z), ftf(g0.w), ftf(g1.w));
}

__global__ __launch_bounds__(256) void preround_w(const float4* __restrict__ wq,
                                                  const float4* __restrict__ wk,
                                                  const float4* __restrict__ wv) {
    const int g = blockIdx.x * 256 + threadIdx.x;
    const int z = blockIdx.y;
    const float4* src = (z == 0) ? wq : (z == 1) ? wk : wv;
    const float4 g0 = src[2 * g], g1 = src[2 * g + 1];
    float4* dst = (float4*)g_wr + (size_t)z * 262144 + 2 * g;
    dst[0] = make_float4(ftf(g0.x), ftf(g1.x), ftf(g0.y), ftf(g1.y));
    dst[1] = make_float4(ftf(g0.z), ftf(g1.z), ftf(g0.w), ftf(g1.w));
}

// ---------------- Phase 1: fused QKV projection ----------------
// 128x128 CTA tile, 64x32 warptile, 3-stage cp.async ring, smem stride 36,
// one __syncthreads per ktile.
#define SSTR 36
#define STG_F (128 * SSTR)           // floats per matrix per stage (4608)

__global__ __launch_bounds__(256, 2) void gemm_qkv(
    const float* __restrict__ bq, const float* __restrict__ bk, const float* __restrict__ bv)
{
    extern __shared__ float sm1[];   // [3 stages][A 4608 | B 4608]

    const int z = blockIdx.z;
    const float* X    = g_xr + (size_t)z * (M_TOT * E_DIM);
    const float* W    = g_wr + (size_t)z * (E_DIM * E_DIM);
    const float* bias = (z == 0) ? bq : (z == 1) ? bk : bv;
    float* dst        = (z == 0) ? g_q : (z == 1) ? g_k : g_v;
    const bool do_relu = (z < 2);

    const int m0 = blockIdx.y * 128;
    const int n0 = blockIdx.x * 128;
    const int t = threadIdx.x;
    const int lane = t & 31, warp = t >> 5;
    const int wm = (warp & 1) * 64, wn = (warp >> 1) * 32;
    const int gid = lane >> 2, tig = lane & 3;

    const int lr = t >> 3;          // 0..31
    const int lc = (t & 7) * 4;     // 0..28
    const float* Ag = X + (size_t)(m0 + lr) * E_DIM + lc;
    const float* Bg = W + (size_t)(n0 + lr) * E_DIM + lc;

    float acc[4][4][4];
#pragma unroll
    for (int i = 0; i < 4; ++i)
#pragma unroll
        for (int j = 0; j < 4; ++j)
#pragma unroll
            for (int e = 0; e < 4; ++e) acc[i][j][e] = 0.f;

    auto stage = [&](int kt) {
        float* sA = sm1 + (kt % 3) * (2 * STG_F);
        float* sB = sA + STG_F;
#pragma unroll
        for (int i = 0; i < 4; ++i) {
            cpa16(&sA[(lr + i * 32) * SSTR + lc], Ag + kt * 32 + (size_t)i * 32 * E_DIM);
            cpa16(&sB[(lr + i * 32) * SSTR + lc], Bg + kt * 32 + (size_t)i * 32 * E_DIM);
        }
        asm volatile("cp.async.commit_group;\n");
    };

    stage(0);
    stage(1);
#pragma unroll 1
    for (int kt = 0; kt < 32; ++kt) {
        if (kt < 31) asm volatile("cp.async.wait_group 1;\n");
        else         asm volatile("cp.async.wait_group 0;\n");
        __syncthreads();
        if (kt < 30) stage(kt + 2);

        const float* sA = sm1 + (kt % 3) * (2 * STG_F);
        const float* sB = sA + STG_F;
#pragma unroll
        for (int k8 = 0; k8 < 4; ++k8) {
            const int kk = k8 * 8;
            float2 aA[4][2];
            float2 bB[4];
#pragma unroll
            for (int mf = 0; mf < 4; ++mf) {
                const int r = wm + mf * 16 + gid;
                aA[mf][0] = *(const float2*)&sA[r * SSTR + kk + tig * 2];
                aA[mf][1] = *(const float2*)&sA[(r + 8) * SSTR + kk + tig * 2];
            }
#pragma unroll
            for (int nf = 0; nf < 4; ++nf) {
                const int cb = wn + nf * 8 + gid;
                bB[nf] = *(const float2*)&sB[cb * SSTR + kk + tig * 2];
            }
#pragma unroll
            for (int mf = 0; mf < 4; ++mf)
#pragma unroll
                for (int nf = 0; nf < 4; ++nf)
                    mma_tf32(acc[mf][nf],
                             __float_as_uint(aA[mf][0].x), __float_as_uint(aA[mf][1].x),
                             __float_as_uint(aA[mf][0].y), __float_as_uint(aA[mf][1].y),
                             __float_as_uint(bB[nf].x),    __float_as_uint(bB[nf].y));
        }
    }
    __syncthreads();

    // epilogue: bias + relu + scatter to [head][l][hd]
#pragma unroll
    for (int mf = 0; mf < 4; ++mf) {
#pragma unroll
        for (int nf = 0; nf < 4; ++nf) {
            const int row = m0 + wm + mf * 16 + gid;
            const int col = n0 + wn + nf * 8 + tig * 2;
#pragma unroll
            for (int e = 0; e < 4; ++e) {
                const int r = row + ((e >= 2) ? 8 : 0);
                const int cc = col + (e & 1);
                float v = acc[mf][nf][e] + __ldg(&bias[cc]);
                if (do_relu) v = fmaxf(v, 0.f);
                const int l = r >> 2, bb = r & 3;
                const int hh = cc >> 6, hd = cc & 63;
                const int head = bb * H_DIM + hh;
                dst[((size_t)head << 18) + ((size_t)l << 6) + (size_t)hd] = v;
            }
        }
    }
}

// ---------------- Phase 2: kv = k_^T v, register-prefetch pipeline ----------------
__global__ __launch_bounds__(256, 2) void kv2() {
    __shared__ float Ks[32 * 136];   // [l][128 scaled d], stride 136
    __shared__ float Vs[32 * 72];    // [l][64 m], stride 72

    const int h = blockIdx.x, ch = blockIdx.y;
    const int t = threadIdx.x, lane = t & 31, warp = t >> 5;
    const int wm = (warp >> 1) * 32, wn = (warp & 1) * 32;
    const int gid = lane >> 2, tig = lane & 3;

    float acc[2][4][4];
#pragma unroll
    for (int mf = 0; mf < 2; ++mf)
#pragma unroll
        for (int nf = 0; nf < 4; ++nf)
#pragma unroll
            for (int e = 0; e < 4; ++e) acc[mf][nf][e] = 0.f;
    float ksacc = 0.f;

    const float* kp = g_k + ((size_t)h << 18);
    const float* vp = g_v + ((size_t)h << 18);
    const int ll = t >> 3;
    const int f = (t & 7) * 8;
    const int ch0 = ch * 512;

    float4 nk0, nk1, nv0, nv1;
    {
        const size_t b = (size_t)(ch0 + ll) * 64 + f;
        nk0 = *(const float4*)(kp + b);     nk1 = *(const float4*)(kp + b + 4);
        nv0 = *(const float4*)(vp + b);     nv1 = *(const float4*)(vp + b + 4);
    }

#pragma unroll 1
    for (int it = 0; it < 16; ++it) {
        {
            const int l = ch0 + it * 32 + ll;
            float s, c;
            sincosf(ANG_C * (float)(l + 1), &s, &c);
            *(float4*)&Ks[ll * 136 + f] =
                make_float4(ftf(nk0.x * s), ftf(nk0.y * s), ftf(nk0.z * s), ftf(nk0.w * s));
            *(float4*)&Ks[ll * 136 + f + 4] =
                make_float4(ftf(nk1.x * s), ftf(nk1.y * s), ftf(nk1.z * s), ftf(nk1.w * s));
            *(float4*)&Ks[ll * 136 + 64 + f] =
                make_float4(ftf(nk0.x * c), ftf(nk0.y * c), ftf(nk0.z * c), ftf(nk0.w * c));
            *(float4*)&Ks[ll * 136 + 64 + f + 4] =
                make_float4(ftf(nk1.x * c), ftf(nk1.y * c), ftf(nk1.z * c), ftf(nk1.w * c));
            *(float4*)&Vs[ll * 72 + f] =
                make_float4(ftf(nv0.x), ftf(nv0.y), ftf(nv0.z), ftf(nv0.w));
            *(float4*)&Vs[ll * 72 + f + 4] =
                make_float4(ftf(nv1.x), ftf(nv1.y), ftf(nv1.z), ftf(nv1.w));
        }
        __syncthreads();
        if (it < 15) {      // prefetch next tile: LDGs overlap with MMAs below
            const size_t b = (size_t)(ch0 + (it + 1) * 32 + ll) * 64 + f;
            nk0 = *(const float4*)(kp + b);     nk1 = *(const float4*)(kp + b + 4);
            nv0 = *(const float4*)(vp + b);     nv1 = *(const float4*)(vp + b + 4);
        }
        if (t < 128) {
#pragma unroll
            for (int j = 0; j < 32; ++j) ksacc += Ks[j * 136 + t];
        }
#pragma unroll
        for (int k8 = 0; k8 < 4; ++k8) {
            const int kk = k8 * 8;
            unsigned af[2][4], bf[4][2];
#pragma unroll
            for (int mf = 0; mf < 2; ++mf) {
                const int r = wm + mf * 16 + gid;
                af[mf][0] = __float_as_uint(Ks[(kk + tig) * 136 + r]);
                af[mf][1] = __float_as_uint(Ks[(kk + tig) * 136 + r + 8]);
                af[mf][2] = __float_as_uint(Ks[(kk + tig + 4) * 136 + r]);
                af[mf][3] = __float_as_uint(Ks[(kk + tig + 4) * 136 + r + 8]);
            }
#pragma unroll
            for (int nf = 0; nf < 4; ++nf) {
                const int cb = wn + nf * 8 + gid;
                bf[nf][0] = __float_as_uint(Vs[(kk + tig) * 72 + cb]);
                bf[nf][1] = __float_as_uint(Vs[(kk + tig + 4) * 72 + cb]);
            }
#pragma unroll
            for (int mf = 0; mf < 2; ++mf)
#pragma unroll
                for (int nf = 0; nf < 4; ++nf)
                    mma_tf32(acc[mf][nf], af[mf][0], af[mf][1], af[mf][2], af[mf][3],
                             bf[nf][0], bf[nf][1]);
        }
        __syncthreads();
    }

    float* outp = g_kv_part + (size_t)(h * NCHUNK + ch) * 8192;
#pragma unroll
    for (int mf = 0; mf < 2; ++mf) {
#pragma unroll
        for (int nf = 0; nf < 4; ++nf) {
            const int row = wm + mf * 16 + gid;
            const int col = wn + nf * 8 + tig * 2;
            *(float2*)&outp[row * 64 + col] = make_float2(acc[mf][nf][0], acc[mf][nf][1]);
            *(float2*)&outp[(row + 8) * 64 + col] = make_float2(acc[mf][nf][2], acc[mf][nf][3]);
        }
    }
    if (t < 128) g_ks_part[(size_t)(h * NCHUNK + ch) * 128 + t] = ksacc;
}

// ---------------- Phase 2b: reduce partials ----------------
__global__ __launch_bounds__(256) void reduce_kv() {
    const int h = blockIdx.x, t = threadIdx.x;
    for (int i = t; i < 8192; i += 256) {
        float s = 0.f;
#pragma unroll
        for (int p = 0; p < NCHUNK; ++p) s += g_kv_part[(size_t)(h * NCHUNK + p) * 8192 + i];
        g_kv[(size_t)h * 8192 + i] = s;
    }
    if (t < 128) {
        float s = 0.f;
#pragma unroll
        for (int p = 0; p < NCHUNK; ++p) s += g_ks_part[(size_t)(h * NCHUNK + p) * 128 + t];
        g_ks[h * 128 + t] = s;
    }
}

// ---------------- Phase 3: out = (q_ @ kv) * z ; 64-l tiles, 2 CTA/SM ----------------
__global__ __launch_bounds__(256, 2) void out2(float* __restrict__ out) {
    extern __shared__ float sm3[];
    float* KVs  = sm3;                     // [128 d][64 m] stride 72 -> 9216 floats
    float* Qs   = sm3 + 9216;              // [64 l][128 d] stride 140 -> 8960 floats
    float* kss  = sm3 + 9216 + 8960;       // [128]
    float* zden = kss + 128;               // [64]

    const int h = blockIdx.x, ch = blockIdx.y;
    const int t = threadIdx.x, lane = t & 31, warp = t >> 5;
    const int wm = (warp >> 2) * 32;       // 0 or 32
    const int wn = (warp & 3) * 16;        // 0,16,32,48
    const int gid = lane >> 2, tig = lane & 3;

    for (int i = t; i < 8192; i += 256) {
        const int r = i >> 6, cn = i & 63;
        KVs[r * 72 + cn] = ftf(g_kv[(size_t)h * 8192 + i]);
    }
    if (t < 128) kss[t] = g_ks[h * 128 + t];

    const float* qp = g_q + ((size_t)h << 18);
    const int bb = h >> 4, hh = h & 15;

#pragma unroll 1
    for (int it = 0; it < 8; ++it) {
        __syncthreads();
        const int l0 = ch * 512 + it * 64;
        {
            const int lq = t >> 2;             // 0..63
            const int fq = (t & 3) * 16;       // 0,16,32,48
            const int l = l0 + lq;
            float s, c;
            sincosf(ANG_C * (float)(l + 1), &s, &c);
            const float* qrow = qp + (size_t)l * 64 + fq;
#pragma unroll
            for (int j = 0; j < 4; ++j) {
                const float4 qv = *(const float4*)(qrow + j * 4);
                *(float4*)&Qs[lq * 140 + fq + j * 4] =
                    make_float4(ftf(qv.x * s), ftf(qv.y * s), ftf(qv.z * s), ftf(qv.w * s));
                *(float4*)&Qs[lq * 140 + 64 + fq + j * 4] =
                    make_float4(ftf(qv.x * c), ftf(qv.y * c), ftf(qv.z * c), ftf(qv.w * c));
            }
        }
        __syncthreads();
        if (t < 128) {
            const int lz = t >> 1;
            const int half = (t & 1) * 64;
            float p = 0.f;
#pragma unroll
            for (int d = 0; d < 64; ++d) p += Qs[lz * 140 + half + d] * kss[half + d];
            p += __shfl_xor_sync(0xffffffffu, p, 1);
            if ((t & 1) == 0) zden[lz] = 1.0f / fmaxf(p, EPS_F);
        }
        __syncthreads();

        float acc[2][2][4];
#pragma unroll
        for (int mf = 0; mf < 2; ++mf)
#pragma unroll
            for (int nf = 0; nf < 2; ++nf)
#pragma unroll
                for (int e = 0; e < 4; ++e) acc[mf][nf][e] = 0.f;

#pragma unroll
        for (int k8 = 0; k8 < 16; ++k8) {
            const int kk = k8 * 8;
            unsigned af[2][4], bf[2][2];
#pragma unroll
            for (int mf = 0; mf < 2; ++mf) {
                const int r = wm + mf * 16 + gid;
                af[mf][0] = __float_as_uint(Qs[r * 140 + kk + tig]);
                af[mf][1] = __float_as_uint(Qs[(r + 8) * 140 + kk + tig]);
                af[mf][2] = __float_as_uint(Qs[r * 140 + kk + tig + 4]);
                af[mf][3] = __float_as_uint(Qs[(r + 8) * 140 + kk + tig + 4]);
            }
#pragma unroll
            for (int nf = 0; nf < 2; ++nf) {
                const int cb = wn + nf * 8 + gid;
                bf[nf][0] = __float_as_uint(KVs[(kk + tig) * 72 + cb]);
                bf[nf][1] = __float_as_uint(KVs[(kk + tig + 4) * 72 + cb]);
            }
#pragma unroll
            for (int mf = 0; mf < 2; ++mf)
#pragma unroll
                for (int nf = 0; nf < 2; ++nf)
                    mma_tf32(acc[mf][nf], af[mf][0], af[mf][1], af[mf][2], af[mf][3],
                             bf[nf][0], bf[nf][1]);
        }

#pragma unroll
        for (int mf = 0; mf < 2; ++mf) {
#pragma unroll
            for (int nf = 0; nf < 2; ++nf) {
                const int rl = wm + mf * 16 + gid;
                const int col = hh * 64 + wn + nf * 8 + tig * 2;
                const float z0 = zden[rl];
                const float z1 = zden[rl + 8];
                const int l_a = l0 + rl;
                const int l_b = l_a + 8;
                *(float2*)&out[((size_t)l_a * B_DIM + bb) * E_DIM + col] =
                    make_float2(acc[mf][nf][0] * z0, acc[mf][nf][1] * z0);
                *(float2*)&out[((size_t)l_b * B_DIM + bb) * E_DIM + col] =
                    make_float2(acc[mf][nf][2] * z1, acc[mf][nf][3] * z1);
            }
        }
    }
}

// ---------------- launch ----------------
extern "C" void kernel_launch(void* const* d_in, const int* in_sizes, int n_in,
                              void* d_out, int out_size) {
    const float* q  = (const float*)d_in[0];
    const float* k  = (const float*)d_in[1];
    const float* v  = (const float*)d_in[2];
    const float* Wq = (const float*)d_in[3];
    const float* bq = (const float*)d_in[4];
    const float* Wk = (const float*)d_in[5];
    const float* bk = (const float*)d_in[6];
    const float* Wv = (const float*)d_in[7];
    const float* bv = (const float*)d_in[8];
    float* out = (float*)d_out;

    const int smem1 = 3 * 2 * STG_F * 4;                    // 110592 B
    const int smem3 = (9216 + 8960 + 128 + 64) * 4;         // 73472 B
    cudaFuncSetAttribute(gemm_qkv, cudaFuncAttributeMaxDynamicSharedMemorySize, smem1);
    cudaFuncSetAttribute(out2, cudaFuncAttributeMaxDynamicSharedMemorySize, smem3);

    preround_x<<<dim3(8192, 3), 256>>>((const float4*)q, (const float4*)k, (const float4*)v);
    preround_w<<<dim3(512, 3), 256>>>((const float4*)Wq, (const float4*)Wk, (const float4*)Wv);
    dim3 g1(E_DIM / 128, M_TOT / 128, 3);   // (8, 128, 3)
    gemm_qkv<<<g1, 256, smem1>>>(bq, bk, bv);
    kv2<<<dim3(NH, NCHUNK), 256>>>();
    reduce_kv<<<NH, 256>>>();
    out2<<<dim3(NH, NCHUNK), 256, smem3>>>(out);
}

// round 7
// speedup vs baseline: 1.7088x; 1.7088x over previous
#include <cuda_runtime.h>
#include <cuda_fp16.h>
#include <cstdint>

#define L_DIM 4096
#define B_DIM 4
#define E_DIM 1024
#define H_DIM 16
#define HD 64
#define NH 64            // B*H
#define M_TOT 16384      // L*B
#define EPS_F 1e-4f
#define ANG_C 3.83495196971410283e-4f   // (pi/2)/4096
#define NCHUNK 8

// ---------------- scratch (device globals; no allocs allowed) ----------------
__device__ float g_q[NH * L_DIM * HD];                 // relu(Q) per head-major
__device__ float g_k[NH * L_DIM * HD];                 // relu(K)
__device__ float g_v[NH * L_DIM * HD];                 // V
__device__ __half g_xh[3 * M_TOT * E_DIM];             // fp16, pair-permuted X (q,k,v)
__device__ __half g_wh[3 * E_DIM * E_DIM];             // fp16, pair-permuted W (q,k,v)
__device__ float g_kv_part[NH * NCHUNK * 2 * HD * HD]; // per-chunk partial kv [d128][m64]
__device__ float g_ks_part[NH * NCHUNK * 2 * HD];      // per-chunk partial ksum [d128]
__device__ float g_kv[NH * 2 * HD * HD];               // reduced kv
__device__ float g_ks[NH * 2 * HD];                    // reduced ksum

__device__ __forceinline__ unsigned f2tf32(float x) {
    unsigned r;
    asm("cvt.rna.tf32.f32 %0, %1;" : "=r"(r) : "f"(x));
    return r;
}
__device__ __forceinline__ float ftf(float x) { return __uint_as_float(f2tf32(x)); }

__device__ __forceinline__ void mma_tf32(float c[4],
                                         unsigned a0, unsigned a1, unsigned a2, unsigned a3,
                                         unsigned b0, unsigned b1) {
    asm volatile(
        "mma.sync.aligned.m16n8k8.row.col.f32.tf32.tf32.f32 "
        "{%0,%1,%2,%3}, {%4,%5,%6,%7}, {%8,%9}, {%0,%1,%2,%3};\n"
        : "+f"(c[0]), "+f"(c[1]), "+f"(c[2]), "+f"(c[3])
        : "r"(a0), "r"(a1), "r"(a2), "r"(a3), "r"(b0), "r"(b1));
}

__device__ __forceinline__ void mma_f16(float c[4],
                                        unsigned a0, unsigned a1, unsigned a2, unsigned a3,
                                        unsigned b0, unsigned b1) {
    asm volatile(
        "mma.sync.aligned.m16n8k16.row.col.f32.f16.f16.f32 "
        "{%0,%1,%2,%3}, {%4,%5,%6,%7}, {%8,%9}, {%0,%1,%2,%3};\n"
        : "+f"(c[0]), "+f"(c[1]), "+f"(c[2]), "+f"(c[3])
        : "r"(a0), "r"(a1), "r"(a2), "r"(a3), "r"(b0), "r"(b1));
}

__device__ __forceinline__ void cpa16(void* dst, const void* src) {
    unsigned d = (unsigned)__cvta_generic_to_shared(dst);
    asm volatile("cp.async.cg.shared.global [%0], [%1], 16;\n" :: "r"(d), "l"(src));
}

// ---------------- Phase 0: fp16-round + pair-permute X and W ----------------
// 16-group [k0..k15] stored as half2 pairs [p0,p4,p1,p5,p2,p6,p3,p7] (p_j = (k2j,k2j+1)).
// Then lane tig reads halves [tig*4 .. tig*4+3] = pairs (tig, tig+4) = exactly the
// m16n8k16 fragment k-pairs -> one LDS.64 per fragment.
__global__ __launch_bounds__(256) void preround_x(const float4* __restrict__ xq,
                                                  const float4* __restrict__ xk,
                                                  const float4* __restrict__ xv) {
    const int g = blockIdx.x * 256 + threadIdx.x;     // 16-float group id
    const int z = blockIdx.y;
    const float4* src = (z == 0) ? xq : (z == 1) ? xk : xv;
    const float4 f0 = src[4 * g + 0];
    const float4 f1 = src[4 * g + 1];
    const float4 f2 = src[4 * g + 2];
    const float4 f3 = src[4 * g + 3];
    __half2 h[8];
    h[0] = __floats2half2_rn(f0.x, f0.y);   // p0
    h[1] = __floats2half2_rn(f2.x, f2.y);   // p4
    h[2] = __floats2half2_rn(f0.z, f0.w);   // p1
    h[3] = __floats2half2_rn(f2.z, f2.w);   // p5
    h[4] = __floats2half2_rn(f1.x, f1.y);   // p2
    h[5] = __floats2half2_rn(f3.x, f3.y);   // p6
    h[6] = __floats2half2_rn(f1.z, f1.w);   // p3
    h[7] = __floats2half2_rn(f3.z, f3.w);   // p7
    float4* dst = (float4*)g_xh + (size_t)z * 2097152 + 2 * (size_t)g;
    dst[0] = *(float4*)&h[0];
    dst[1] = *(float4*)&h[4];
}

__global__ __launch_bounds__(256) void preround_w(const float4* __restrict__ wq,
                                                  const float4* __restrict__ wk,
                                                  const float4* __restrict__ wv) {
    const int g = blockIdx.x * 256 + threadIdx.x;
    const int z = blockIdx.y;
    const float4* src = (z == 0) ? wq : (z == 1) ? wk : wv;
    const float4 f0 = src[4 * g + 0];
    const float4 f1 = src[4 * g + 1];
    const float4 f2 = src[4 * g + 2];
    const float4 f3 = src[4 * g + 3];
    __half2 h[8];
    h[0] = __floats2half2_rn(f0.x, f0.y);
    h[1] = __floats2half2_rn(f2.x, f2.y);
    h[2] = __floats2half2_rn(f0.z, f0.w);
    h[3] = __floats2half2_rn(f2.z, f2.w);
    h[4] = __floats2half2_rn(f1.x, f1.y);
    h[5] = __floats2half2_rn(f3.x, f3.y);
    h[6] = __floats2half2_rn(f1.z, f1.w);
    h[7] = __floats2half2_rn(f3.z, f3.w);
    float4* dst = (float4*)g_wh + (size_t)z * 131072 + 2 * (size_t)g;
    dst[0] = *(float4*)&h[0];
    dst[1] = *(float4*)&h[4];
}

// ---------------- Phase 1: fused QKV projection (fp16 m16n8k16) ----------------
// 128x128 CTA tile, 64x32 warptile, cp.async double buffer, smem stride 48 halves.
#define SSTRH 48
#define STGH (128 * SSTRH)           // halves per matrix per stage (6144)

__global__ __launch_bounds__(256, 2) void gemm_qkv(
    const float* __restrict__ bq, const float* __restrict__ bk, const float* __restrict__ bv)
{
    extern __shared__ __half smh[];  // [2 stages][A 6144 | B 6144]

    const int z = blockIdx.z;
    const __half* X   = g_xh + (size_t)z * (M_TOT * E_DIM);
    const __half* W   = g_wh + (size_t)z * (E_DIM * E_DIM);
    const float* bias = (z == 0) ? bq : (z == 1) ? bk : bv;
    float* dst        = (z == 0) ? g_q : (z == 1) ? g_k : g_v;
    const bool do_relu = (z < 2);

    const int m0 = blockIdx.y * 128;
    const int n0 = blockIdx.x * 128;
    const int t = threadIdx.x;
    const int lane = t & 31, warp = t >> 5;
    const int wm = (warp & 1) * 64, wn = (warp >> 1) * 32;
    const int gid = lane >> 2, tig = lane & 3;

    const int lr4 = t >> 2;          // 0..63
    const int seg = (t & 3) * 8;     // halves offset: 0,8,16,24
    const __half* Ag = X + (size_t)m0 * E_DIM;
    const __half* Bg = W + (size_t)n0 * E_DIM;

    float acc[4][4][4];
#pragma unroll
    for (int i = 0; i < 4; ++i)
#pragma unroll
        for (int j = 0; j < 4; ++j)
#pragma unroll
            for (int e = 0; e < 4; ++e) acc[i][j][e] = 0.f;

    auto stage = [&](int kt, int buf) {
        __half* sA = smh + buf * (2 * STGH);
        __half* sB = sA + STGH;
#pragma unroll
        for (int i = 0; i < 2; ++i) {
            const int row = lr4 + i * 64;
            cpa16(&sA[row * SSTRH + seg], Ag + (size_t)row * E_DIM + kt * 32 + seg);
            cpa16(&sB[row * SSTRH + seg], Bg + (size_t)row * E_DIM + kt * 32 + seg);
        }
        asm volatile("cp.async.commit_group;\n");
    };

    stage(0, 0);
#pragma unroll 1
    for (int kt = 0; kt < 32; ++kt) {
        if (kt < 31) {
            stage(kt + 1, (kt + 1) & 1);
            asm volatile("cp.async.wait_group 1;\n");
        } else {
            asm volatile("cp.async.wait_group 0;\n");
        }
        __syncthreads();
        const __half* sA = smh + (kt & 1) * (2 * STGH);
        const __half* sB = sA + STGH;
#pragma unroll
        for (int s = 0; s < 2; ++s) {
            const int kpos = s * 16 + tig * 4;
            uint2 aF[4][2];
            uint2 bF[4];
#pragma unroll
            for (int mf = 0; mf < 4; ++mf) {
                const int r = wm + mf * 16 + gid;
                aF[mf][0] = *(const uint2*)&sA[r * SSTRH + kpos];
                aF[mf][1] = *(const uint2*)&sA[(r + 8) * SSTRH + kpos];
            }
#pragma unroll
            for (int nf = 0; nf < 4; ++nf) {
                const int cb = wn + nf * 8 + gid;
                bF[nf] = *(const uint2*)&sB[cb * SSTRH + kpos];
            }
#pragma unroll
            for (int mf = 0; mf < 4; ++mf)
#pragma unroll
                for (int nf = 0; nf < 4; ++nf)
                    mma_f16(acc[mf][nf],
                            aF[mf][0].x, aF[mf][1].x, aF[mf][0].y, aF[mf][1].y,
                            bF[nf].x, bF[nf].y);
        }
        __syncthreads();
    }

    // epilogue: bias + relu + scatter to [head][l][hd]
#pragma unroll
    for (int mf = 0; mf < 4; ++mf) {
#pragma unroll
        for (int nf = 0; nf < 4; ++nf) {
            const int row = m0 + wm + mf * 16 + gid;
            const int col = n0 + wn + nf * 8 + tig * 2;
#pragma unroll
            for (int e = 0; e < 4; ++e) {
                const int r = row + ((e >= 2) ? 8 : 0);
                const int cc = col + (e & 1);
                float v = acc[mf][nf][e] + __ldg(&bias[cc]);
                if (do_relu) v = fmaxf(v, 0.f);
                const int l = r >> 2, bb = r & 3;
                const int hh = cc >> 6, hd = cc & 63;
                const int head = bb * H_DIM + hh;
                dst[((size_t)head << 18) + ((size_t)l << 6) + (size_t)hd] = v;
            }
        }
    }
}

// ---------------- Phase 2: kv = k_^T v, register-prefetch pipeline ----------------
__global__ __launch_bounds__(256, 2) void kv2() {
    __shared__ float Ks[32 * 136];   // [l][128 scaled d], stride 136
    __shared__ float Vs[32 * 72];    // [l][64 m], stride 72

    const int h = blockIdx.x, ch = blockIdx.y;
    const int t = threadIdx.x, lane = t & 31, warp = t >> 5;
    const int wm = (warp >> 1) * 32, wn = (warp & 1) * 32;
    const int gid = lane >> 2, tig = lane & 3;

    float acc[2][4][4];
#pragma unroll
    for (int mf = 0; mf < 2; ++mf)
#pragma unroll
        for (int nf = 0; nf < 4; ++nf)
#pragma unroll
            for (int e = 0; e < 4; ++e) acc[mf][nf][e] = 0.f;
    float ksacc = 0.f;

    const float* kp = g_k + ((size_t)h << 18);
    const float* vp = g_v + ((size_t)h << 18);
    const int ll = t >> 3;
    const int f = (t & 7) * 8;
    const int ch0 = ch * 512;

    float4 nk0, nk1, nv0, nv1;
    {
        const size_t b = (size_t)(ch0 + ll) * 64 + f;
        nk0 = *(const float4*)(kp + b);     nk1 = *(const float4*)(kp + b + 4);
        nv0 = *(const float4*)(vp + b);     nv1 = *(const float4*)(vp + b + 4);
    }

#pragma unroll 1
    for (int it = 0; it < 16; ++it) {
        {
            const int l = ch0 + it * 32 + ll;
            float s, c;
            sincosf(ANG_C * (float)(l + 1), &s, &c);
            *(float4*)&Ks[ll * 136 + f] =
                make_float4(ftf(nk0.x * s), ftf(nk0.y * s), ftf(nk0.z * s), ftf(nk0.w * s));
            *(float4*)&Ks[ll * 136 + f + 4] =
                make_float4(ftf(nk1.x * s), ftf(nk1.y * s), ftf(nk1.z * s), ftf(nk1.w * s));
            *(float4*)&Ks[ll * 136 + 64 + f] =
                make_float4(ftf(nk0.x * c), ftf(nk0.y * c), ftf(nk0.z * c), ftf(nk0.w * c));
            *(float4*)&Ks[ll * 136 + 64 + f + 4] =
                make_float4(ftf(nk1.x * c), ftf(nk1.y * c), ftf(nk1.z * c), ftf(nk1.w * c));
            *(float4*)&Vs[ll * 72 + f] =
                make_float4(ftf(nv0.x), ftf(nv0.y), ftf(nv0.z), ftf(nv0.w));
            *(float4*)&Vs[ll * 72 + f + 4] =
                make_float4(ftf(nv1.x), ftf(nv1.y), ftf(nv1.z), ftf(nv1.w));
        }
        __syncthreads();
        if (it < 15) {      // prefetch next tile: LDGs overlap with MMAs below
            const size_t b = (size_t)(ch0 + (it + 1) * 32 + ll) * 64 + f;
            nk0 = *(const float4*)(kp + b);     nk1 = *(const float4*)(kp + b + 4);
            nv0 = *(const float4*)(vp + b);     nv1 = *(const float4*)(vp + b + 4);
        }
        if (t < 128) {
#pragma unroll
            for (int j = 0; j < 32; ++j) ksacc += Ks[j * 136 + t];
        }
#pragma unroll
        for (int k8 = 0; k8 < 4; ++k8) {
            const int kk = k8 * 8;
            unsigned af[2][4], bf[4][2];
#pragma unroll
            for (int mf = 0; mf < 2; ++mf) {
                const int r = wm + mf * 16 + gid;
                af[mf][0] = __float_as_uint(Ks[(kk + tig) * 136 + r]);
                af[mf][1] = __float_as_uint(Ks[(kk + tig) * 136 + r + 8]);
                af[mf][2] = __float_as_uint(Ks[(kk + tig + 4) * 136 + r]);
                af[mf][3] = __float_as_uint(Ks[(kk + tig + 4) * 136 + r + 8]);
            }
#pragma unroll
            for (int nf = 0; nf < 4; ++nf) {
                const int cb = wn + nf * 8 + gid;
                bf[nf][0] = __float_as_uint(Vs[(kk + tig) * 72 + cb]);
                bf[nf][1] = __float_as_uint(Vs[(kk + tig + 4) * 72 + cb]);
            }
#pragma unroll
            for (int mf = 0; mf < 2; ++mf)
#pragma unroll
                for (int nf = 0; nf < 4; ++nf)
                    mma_tf32(acc[mf][nf], af[mf][0], af[mf][1], af[mf][2], af[mf][3],
                             bf[nf][0], bf[nf][1]);
        }
        __syncthreads();
    }

    float* outp = g_kv_part + (size_t)(h * NCHUNK + ch) * 8192;
#pragma unroll
    for (int mf = 0; mf < 2; ++mf) {
#pragma unroll
        for (int nf = 0; nf < 4; ++nf) {
            const int row = wm + mf * 16 + gid;
            const int col = wn + nf * 8 + tig * 2;
            *(float2*)&outp[row * 64 + col] = make_float2(acc[mf][nf][0], acc[mf][nf][1]);
            *(float2*)&outp[(row + 8) * 64 + col] = make_float2(acc[mf][nf][2], acc[mf][nf][3]);
        }
    }
    if (t < 128) g_ks_part[(size_t)(h * NCHUNK + ch) * 128 + t] = ksacc;
}

// ---------------- Phase 2b: reduce partials ----------------
__global__ __launch_bounds__(256) void reduce_kv() {
    const int h = blockIdx.x, t = threadIdx.x;
    for (int i = t; i < 8192; i += 256) {
        float s = 0.f;
#pragma unroll
        for (int p = 0; p < NCHUNK; ++p) s += g_kv_part[(size_t)(h * NCHUNK + p) * 8192 + i];
        g_kv[(size_t)h * 8192 + i] = s;
    }
    if (t < 128) {
        float s = 0.f;
#pragma unroll
        for (int p = 0; p < NCHUNK; ++p) s += g_ks_part[(size_t)(h * NCHUNK + p) * 128 + t];
        g_ks[h * 128 + t] = s;
    }
}

// ---------------- Phase 3: out = (q_ @ kv) * z via tensor cores ----------------
__global__ __launch_bounds__(256, 1) void out2(float* __restrict__ out) {
    extern __shared__ float sm3[];
    float* KVs  = sm3;                     // [128 d][64 m] stride 72  -> 9216 floats
    float* Qs   = sm3 + 9216;              // [128 l][128 d] stride 140 -> 17920 floats
    float* kss  = sm3 + 9216 + 17920;      // [128]
    float* zden = kss + 128;               // [128]

    const int h = blockIdx.x, ch = blockIdx.y;
    const int t = threadIdx.x, lane = t & 31, warp = t >> 5;
    const int wm = (warp >> 1) * 32, wn = (warp & 1) * 32;
    const int gid = lane >> 2, tig = lane & 3;

    for (int i = t; i < 8192; i += 256) {
        const int r = i >> 6, cn = i & 63;
        KVs[r * 72 + cn] = ftf(g_kv[(size_t)h * 8192 + i]);
    }
    if (t < 128) kss[t] = g_ks[h * 128 + t];

    const float* qp = g_q + ((size_t)h << 18);
    const int bb = h >> 4, hh = h & 15;

#pragma unroll 1
    for (int it = 0; it < 4; ++it) {
        __syncthreads();
        const int l0 = ch * 512 + it * 128;
        {
            const int lq = t >> 1;
            const int fq = (t & 1) * 32;
            const int l = l0 + lq;
            float s, c;
            sincosf(ANG_C * (float)(l + 1), &s, &c);
            const float* qrow = qp + (size_t)l * 64 + fq;
#pragma unroll
            for (int j = 0; j < 8; ++j) {
                const float4 qv = *(const float4*)(qrow + j * 4);
                *(float4*)&Qs[lq * 140 + fq + j * 4] =
                    make_float4(ftf(qv.x * s), ftf(qv.y * s), ftf(qv.z * s), ftf(qv.w * s));
                *(float4*)&Qs[lq * 140 + 64 + fq + j * 4] =
                    make_float4(ftf(qv.x * c), ftf(qv.y * c), ftf(qv.z * c), ftf(qv.w * c));
            }
        }
        __syncthreads();
        {
            const int lz = t >> 1;
            const int half = (t & 1) * 64;
            float p = 0.f;
#pragma unroll
            for (int d = 0; d < 64; ++d) p += Qs[lz * 140 + half + d] * kss[half + d];
            p += __shfl_xor_sync(0xffffffffu, p, 1);
            if ((t & 1) == 0) zden[lz] = 1.0f / fmaxf(p, EPS_F);
        }
        __syncthreads();

        float acc[2][4][4];
#pragma unroll
        for (int mf = 0; mf < 2; ++mf)
#pragma unroll
            for (int nf = 0; nf < 4; ++nf)
#pragma unroll
                for (int e = 0; e < 4; ++e) acc[mf][nf][e] = 0.f;

#pragma unroll
        for (int k8 = 0; k8 < 16; ++k8) {
            const int kk = k8 * 8;
            unsigned af[2][4], bf[4][2];
#pragma unroll
            for (int mf = 0; mf < 2; ++mf) {
                const int r = wm + mf * 16 + gid;
                af[mf][0] = __float_as_uint(Qs[r * 140 + kk + tig]);
                af[mf][1] = __float_as_uint(Qs[(r + 8) * 140 + kk + tig]);
                af[mf][2] = __float_as_uint(Qs[r * 140 + kk + tig + 4]);
                af[mf][3] = __float_as_uint(Qs[(r + 8) * 140 + kk + tig + 4]);
            }
#pragma unroll
            for (int nf = 0; nf < 4; ++nf) {
                const int cb = wn + nf * 8 + gid;
                bf[nf][0] = __float_as_uint(KVs[(kk + tig) * 72 + cb]);
                bf[nf][1] = __float_as_uint(KVs[(kk + tig + 4) * 72 + cb]);
            }
#pragma unroll
            for (int mf = 0; mf < 2; ++mf)
#pragma unroll
                for (int nf = 0; nf < 4; ++nf)
                    mma_tf32(acc[mf][nf], af[mf][0], af[mf][1], af[mf][2], af[mf][3],
                             bf[nf][0], bf[nf][1]);
        }

#pragma unroll
        for (int mf = 0; mf < 2; ++mf) {
#pragma unroll
            for (int nf = 0; nf < 4; ++nf) {
                const int rl = wm + mf * 16 + gid;
                const int col = hh * 64 + wn + nf * 8 + tig * 2;
                const float z0 = zden[rl];
                const float z1 = zden[rl + 8];
                const int l_a = l0 + rl;
                const int l_b = l_a + 8;
                *(float2*)&out[((size_t)l_a * B_DIM + bb) * E_DIM + col] =
                    make_float2(acc[mf][nf][0] * z0, acc[mf][nf][1] * z0);
                *(float2*)&out[((size_t)l_b * B_DIM + bb) * E_DIM + col] =
                    make_float2(acc[mf][nf][2] * z1, acc[mf][nf][3] * z1);
            }
        }
    }
}

// ---------------- launch ----------------
extern "C" void kernel_launch(void* const* d_in, const int* in_sizes, int n_in,
                              void* d_out, int out_size) {
    const float* q  = (const float*)d_in[0];
    const float* k  = (const float*)d_in[1];
    const float* v  = (const float*)d_in[2];
    const float* Wq = (const float*)d_in[3];
    const float* bq = (const float*)d_in[4];
    const float* Wk = (const float*)d_in[5];
    const float* bk = (const float*)d_in[6];
    const float* Wv = (const float*)d_in[7];
    const float* bv = (const float*)d_in[8];
    float* out = (float*)d_out;

    const int smem1 = 2 * 2 * STGH * 2;                     // 49152 B
    const int smem3 = (9216 + 17920 + 256) * 4;             // 109568 B
    cudaFuncSetAttribute(gemm_qkv, cudaFuncAttributeMaxDynamicSharedMemorySize, smem1);
    cudaFuncSetAttribute(out2, cudaFuncAttributeMaxDynamicSharedMemorySize, smem3);

    preround_x<<<dim3(4096, 3), 256>>>((const float4*)q, (const float4*)k, (const float4*)v);
    preround_w<<<dim3(256, 3), 256>>>((const float4*)Wq, (const float4*)Wk, (const float4*)Wv);
    dim3 g1(E_DIM / 128, M_TOT / 128, 3);   // (8, 128, 3)
    gemm_qkv<<<g1, 256, smem1>>>(bq, bk, bv);
    kv2<<<dim3(NH, NCHUNK), 256>>>();
    reduce_kv<<<NH, 256>>>();
    out2<<<dim3(NH, NCHUNK), 256, smem3>>>(out);
}